// round 2
// baseline (speedup 1.0000x reference)
#include <cuda_runtime.h>
#include <cuda_bf16.h>
#include <cstdint>
#include <cstddef>

#define NN 40000
#define EE 60000
#define RR 6
#define ETOT (EE + NN)          // 100000 edges per relation incl self-loops
#define RN (RR * NN)            // 240000
#define HC 256                  // H*C
#define HID 128
#define BGRAPH 2000
#define SCAN_NB ((RN + 1023) / 1024)   // 235

// ---------------- scratch (static device globals; no runtime allocation) ----
static __device__ float g_XL[61440000];   // [R][N][256]
static __device__ float g_XR[61440000];   // [R][N][256]
static __device__ float g_H[NN * HID];    // node features between layers / final
static __device__ int   g_counts[RN];
static __device__ int   g_offsets[RN];
static __device__ int   g_cursor[RN];
static __device__ int   g_srcs[RR * ETOT];
static __device__ int   g_bsum[SCAN_NB];

// ---------------- CSR construction -----------------------------------------
__global__ void k_init_counts() {
    int i = blockIdx.x * blockDim.x + threadIdx.x;
    if (i < RN) g_counts[i] = 1;          // 1 == self-loop
}

__global__ void k_hist(const int* __restrict__ ei) {
    int i = blockIdx.x * blockDim.x + threadIdx.x;
    if (i >= RR * EE) return;
    int r = i / EE, e = i - r * EE;
    int dst = ei[(r * 2 + 1) * EE + e];
    atomicAdd(&g_counts[r * NN + dst], 1);
}

__global__ void k_scan1() {
    __shared__ int wsum[8];
    int tid = threadIdx.x;
    int i0 = blockIdx.x * 1024 + tid * 4;
    int4 v = make_int4(0, 0, 0, 0);
    bool ok = (i0 < RN);
    if (ok) v = *(const int4*)&g_counts[i0];
    int s0 = v.x, s1 = s0 + v.y, s2 = s1 + v.z, s3 = s2 + v.w;
    int lane = tid & 31, w = tid >> 5;
    int sc = s3;
#pragma unroll
    for (int off = 1; off < 32; off <<= 1) {
        int t = __shfl_up_sync(0xffffffffu, sc, off);
        if (lane >= off) sc += t;
    }
    if (lane == 31) wsum[w] = sc;
    __syncthreads();
    if (tid == 0) {
        int run = 0;
#pragma unroll
        for (int j = 0; j < 8; j++) { int t = wsum[j]; wsum[j] = run; run += t; }
        g_bsum[blockIdx.x] = run;
    }
    __syncthreads();
    int excl = wsum[w] + sc - s3;
    if (ok) {
        g_offsets[i0 + 0] = excl;
        g_offsets[i0 + 1] = excl + s0;
        g_offsets[i0 + 2] = excl + s1;
        g_offsets[i0 + 3] = excl + s2;
    }
}

__global__ void k_scan2() {
    __shared__ int wsum[8];
    int tid = threadIdx.x;
    int v = (tid < SCAN_NB) ? g_bsum[tid] : 0;
    int lane = tid & 31, w = tid >> 5;
    int s = v;
#pragma unroll
    for (int off = 1; off < 32; off <<= 1) {
        int t = __shfl_up_sync(0xffffffffu, s, off);
        if (lane >= off) s += t;
    }
    if (lane == 31) wsum[w] = s;
    __syncthreads();
    if (tid == 0) {
        int run = 0;
#pragma unroll
        for (int j = 0; j < 8; j++) { int t = wsum[j]; wsum[j] = run; run += t; }
    }
    __syncthreads();
    int excl = wsum[w] + s - v;
    if (tid < SCAN_NB) g_bsum[tid] = excl;
}

__global__ void k_scan3() {
    int i0 = blockIdx.x * 1024 + threadIdx.x * 4;
    if (i0 >= RN) return;
    int base = g_bsum[blockIdx.x];
    int4 o = *(const int4*)&g_offsets[i0];
    o.x += base; o.y += base; o.z += base; o.w += base;
    *(int4*)&g_offsets[i0] = o;
    *(int4*)&g_cursor[i0] = o;
}

__global__ void k_scatter(const int* __restrict__ ei) {
    int i = blockIdx.x * blockDim.x + threadIdx.x;
    if (i >= RR * ETOT) return;
    int r = i / ETOT, j = i - r * ETOT;
    int src, dst;
    if (j < EE) {
        src = ei[(r * 2 + 0) * EE + j];
        dst = ei[(r * 2 + 1) * EE + j];
    } else {
        src = j - EE; dst = src;        // self-loop
    }
    int pos = atomicAdd(&g_cursor[r * NN + dst], 1);
    g_srcs[pos] = src;
}

// ---------------- tf32 tensor-core GEMM: Y[rs] = X @ W[rs] + b[rs] ----------
__device__ __forceinline__ uint32_t f2tf32(float x) {
    uint32_t u;
    asm("cvt.rna.tf32.f32 %0, %1;" : "=r"(u) : "f"(x));
    return u;
}
__device__ __forceinline__ void mma8(float* d, const uint32_t* a, uint32_t b0, uint32_t b1) {
    asm volatile(
        "mma.sync.aligned.m16n8k8.row.col.f32.tf32.tf32.f32 "
        "{%0,%1,%2,%3}, {%4,%5,%6,%7}, {%8,%9}, {%0,%1,%2,%3};"
        : "+f"(d[0]), "+f"(d[1]), "+f"(d[2]), "+f"(d[3])
        : "r"(a[0]), "r"(a[1]), "r"(a[2]), "r"(a[3]), "r"(b0), "r"(b1));
}

// block: 256 thr (8 warps, 2x4 layout), tile BM=64 x BN=256, BK=32
__global__ __launch_bounds__(256) void k_gemm(
    const float* __restrict__ Xext, int F,
    const float* __restrict__ Wl, const float* __restrict__ Wr,
    const float* __restrict__ bl, const float* __restrict__ br)
{
    const float* X = Xext ? Xext : g_H;
    int rs = blockIdx.y;
    int r = (rs < RR) ? rs : rs - RR;
    const float* W    = ((rs < RR) ? Wl : Wr) + (size_t)r * F * HC;
    const float* bias = ((rs < RR) ? bl : br) + (size_t)r * HC;
    float* Y          = ((rs < RR) ? g_XL : g_XR) + (size_t)r * NN * HC;

    __shared__ float Xs[64][36];     // pad 36: conflict-free A frag loads
    __shared__ float Ws[32][264];    // pad 264: conflict-free B frag loads
    int tid = threadIdx.x, lane = tid & 31, warp = tid >> 5;
    int wm = warp >> 2, wn = warp & 3;
    int gid = lane >> 2, tg = lane & 3;
    int rowBase = blockIdx.x * 64;

    float acc[2][8][4];
#pragma unroll
    for (int a = 0; a < 2; a++)
#pragma unroll
        for (int b = 0; b < 8; b++)
#pragma unroll
            for (int c = 0; c < 4; c++) acc[a][b][c] = 0.f;

    int xrow = tid >> 2, xcol = (tid & 3) * 8;
    int wrow = tid >> 3, wcol = (tid & 7) * 32;

    for (int kc = 0; kc < F; kc += 32) {
        const float* xp = X + (size_t)(rowBase + xrow) * F + kc + xcol;
        float4 v0 = *(const float4*)xp;
        float4 v1 = *(const float4*)(xp + 4);
        Xs[xrow][xcol + 0] = __uint_as_float(f2tf32(v0.x));
        Xs[xrow][xcol + 1] = __uint_as_float(f2tf32(v0.y));
        Xs[xrow][xcol + 2] = __uint_as_float(f2tf32(v0.z));
        Xs[xrow][xcol + 3] = __uint_as_float(f2tf32(v0.w));
        Xs[xrow][xcol + 4] = __uint_as_float(f2tf32(v1.x));
        Xs[xrow][xcol + 5] = __uint_as_float(f2tf32(v1.y));
        Xs[xrow][xcol + 6] = __uint_as_float(f2tf32(v1.z));
        Xs[xrow][xcol + 7] = __uint_as_float(f2tf32(v1.w));
        const float* wp = W + (size_t)(kc + wrow) * HC + wcol;
#pragma unroll
        for (int j = 0; j < 8; j++) {
            float4 wv = *(const float4*)(wp + j * 4);
            Ws[wrow][wcol + j * 4 + 0] = __uint_as_float(f2tf32(wv.x));
            Ws[wrow][wcol + j * 4 + 1] = __uint_as_float(f2tf32(wv.y));
            Ws[wrow][wcol + j * 4 + 2] = __uint_as_float(f2tf32(wv.z));
            Ws[wrow][wcol + j * 4 + 3] = __uint_as_float(f2tf32(wv.w));
        }
        __syncthreads();
#pragma unroll
        for (int kt = 0; kt < 4; kt++) {
            int k0 = kt * 8;
            uint32_t af[2][4];
#pragma unroll
            for (int mt = 0; mt < 2; mt++) {
                int row = wm * 32 + mt * 16 + gid;
                af[mt][0] = __float_as_uint(Xs[row    ][k0 + tg]);
                af[mt][1] = __float_as_uint(Xs[row + 8][k0 + tg]);
                af[mt][2] = __float_as_uint(Xs[row    ][k0 + tg + 4]);
                af[mt][3] = __float_as_uint(Xs[row + 8][k0 + tg + 4]);
            }
#pragma unroll
            for (int nt = 0; nt < 8; nt++) {
                int col = wn * 64 + nt * 8 + gid;
                uint32_t b0 = __float_as_uint(Ws[k0 + tg    ][col]);
                uint32_t b1 = __float_as_uint(Ws[k0 + tg + 4][col]);
                mma8(acc[0][nt], af[0], b0, b1);
                mma8(acc[1][nt], af[1], b0, b1);
            }
        }
        __syncthreads();
    }
#pragma unroll
    for (int mt = 0; mt < 2; mt++) {
        int gr = rowBase + wm * 32 + mt * 16 + gid;
#pragma unroll
        for (int nt = 0; nt < 8; nt++) {
            int gc = wn * 64 + nt * 8 + 2 * tg;
            float bv0 = bias[gc], bv1 = bias[gc + 1];
            float2 v01; v01.x = acc[mt][nt][0] + bv0; v01.y = acc[mt][nt][1] + bv1;
            float2 v23; v23.x = acc[mt][nt][2] + bv0; v23.y = acc[mt][nt][3] + bv1;
            *(float2*)&Y[(size_t)gr * HC + gc]       = v01;
            *(float2*)&Y[(size_t)(gr + 8) * HC + gc] = v23;
        }
    }
}

// ---------------- GATv2 gather: one warp per node, online softmax -----------
__device__ __forceinline__ float lr4(const float4 xl, const float4 xr, const float4 a) {
    float t, p;
    t = xl.x + xr.x; t = (t > 0.f) ? t : 0.2f * t; p = t * a.x;
    t = xl.y + xr.y; t = (t > 0.f) ? t : 0.2f * t; p = fmaf(t, a.y, p);
    t = xl.z + xr.z; t = (t > 0.f) ? t : 0.2f * t; p = fmaf(t, a.z, p);
    t = xl.w + xr.w; t = (t > 0.f) ? t : 0.2f * t; p = fmaf(t, a.w, p);
    return p;
}

__global__ __launch_bounds__(256) void k_gather(
    const float* __restrict__ att, const float* __restrict__ bias,
    const float* __restrict__ lng, const float* __restrict__ lnb)
{
    int gw = (blockIdx.x * blockDim.x + threadIdx.x) >> 5;
    int lane = threadIdx.x & 31;
    if (gw >= NN) return;
    int n = gw;
    float o0 = 0.f, o1 = 0.f, o2 = 0.f, o3 = 0.f;
#pragma unroll 1
    for (int r = 0; r < RR; r++) {
        const float* xrp = g_XR + ((size_t)r * NN + n) * HC + lane * 4;
        float4 xr0 = *(const float4*)xrp;
        float4 xr1 = *(const float4*)(xrp + 128);
        const float* ap = att + (size_t)r * HC + lane * 4;
        float4 a0 = *(const float4*)ap;
        float4 a1 = *(const float4*)(ap + 128);
        int idx = r * NN + n;
        int start = g_offsets[idx];
        int deg = g_counts[idx];
        float m0 = -1e30f, m1 = -1e30f, s0 = 0.f, s1 = 0.f;
        float4 acc0 = make_float4(0, 0, 0, 0), acc1 = make_float4(0, 0, 0, 0);
        int src = g_srcs[start];
        const float* xlp = g_XL + ((size_t)r * NN + src) * HC + lane * 4;
        float4 xl0 = *(const float4*)xlp;
        float4 xl1 = *(const float4*)(xlp + 128);
#pragma unroll 1
        for (int e = 0; e < deg; e++) {
            float4 c0 = xl0, c1 = xl1;
            if (e + 1 < deg) {
                int s2 = g_srcs[start + e + 1];
                const float* p2 = g_XL + ((size_t)r * NN + s2) * HC + lane * 4;
                xl0 = *(const float4*)p2;
                xl1 = *(const float4*)(p2 + 128);
            }
            float p0 = lr4(c0, xr0, a0);
            float p1 = lr4(c1, xr1, a1);
#pragma unroll
            for (int off = 16; off; off >>= 1) {
                p0 += __shfl_xor_sync(0xffffffffu, p0, off);
                p1 += __shfl_xor_sync(0xffffffffu, p1, off);
            }
            float m0n = fmaxf(m0, p0), m1n = fmaxf(m1, p1);
            float f0 = __expf(m0 - m0n), f1 = __expf(m1 - m1n);
            float w0 = __expf(p0 - m0n), w1 = __expf(p1 - m1n);
            s0 = fmaf(s0, f0, w0); s1 = fmaf(s1, f1, w1);
            acc0.x = fmaf(acc0.x, f0, w0 * c0.x);
            acc0.y = fmaf(acc0.y, f0, w0 * c0.y);
            acc0.z = fmaf(acc0.z, f0, w0 * c0.z);
            acc0.w = fmaf(acc0.w, f0, w0 * c0.w);
            acc1.x = fmaf(acc1.x, f1, w1 * c1.x);
            acc1.y = fmaf(acc1.y, f1, w1 * c1.y);
            acc1.z = fmaf(acc1.z, f1, w1 * c1.z);
            acc1.w = fmaf(acc1.w, f1, w1 * c1.w);
            m0 = m0n; m1 = m1n;
        }
        float i0 = 0.5f / s0, i1 = 0.5f / s1;
        float4 bv = *(const float4*)(bias + (size_t)r * HID + lane * 4);
        o0 += acc0.x * i0 + acc1.x * i1 + bv.x;
        o1 += acc0.y * i0 + acc1.y * i1 + bv.y;
        o2 += acc0.z * i0 + acc1.z * i1 + bv.z;
        o3 += acc0.w * i0 + acc1.w * i1 + bv.w;
    }
    // fused tanh + LayerNorm over 128 channels (4 per lane)
    float t0 = tanhf(o0), t1 = tanhf(o1), t2 = tanhf(o2), t3 = tanhf(o3);
    float sum = t0 + t1 + t2 + t3;
#pragma unroll
    for (int off = 16; off; off >>= 1) sum += __shfl_xor_sync(0xffffffffu, sum, off);
    float mu = sum * (1.f / 128.f);
    float d0 = t0 - mu, d1 = t1 - mu, d2 = t2 - mu, d3 = t3 - mu;
    float vv = d0 * d0 + d1 * d1 + d2 * d2 + d3 * d3;
#pragma unroll
    for (int off = 16; off; off >>= 1) vv += __shfl_xor_sync(0xffffffffu, vv, off);
    float inv = rsqrtf(vv * (1.f / 128.f) + 1e-5f);
    float4 gg = *(const float4*)(lng + lane * 4);
    float4 bb = *(const float4*)(lnb + lane * 4);
    float4 out;
    out.x = d0 * inv * gg.x + bb.x;
    out.y = d1 * inv * gg.y + bb.y;
    out.z = d2 * inv * gg.z + bb.z;
    out.w = d3 * inv * gg.w + bb.w;
    *(float4*)&g_H[(size_t)n * HID + lane * 4] = out;
}

// ---------------- attention pooling over graphs + final projection ----------
__global__ __launch_bounds__(128) void k_pool(
    const float* __restrict__ q, const float* __restrict__ W,
    const float* __restrict__ pb, float* __restrict__ out)
{
    __shared__ float hs[20][128];
    __shared__ float sc[20];
    __shared__ float ww[20];
    __shared__ float gs[128];
    int b = blockIdx.x, t = threadIdx.x;
#pragma unroll
    for (int n = 0; n < 20; n++) hs[n][t] = g_H[(size_t)(b * 20 + n) * HID + t];
    __syncthreads();
    int lane = t & 31, w = t >> 5;
    float4 q4 = *(const float4*)&q[lane * 4];
#pragma unroll
    for (int k = 0; k < 5; k++) {
        int n = w * 5 + k;
        float4 hv = *(const float4*)&hs[n][lane * 4];
        float p = hv.x * q4.x + hv.y * q4.y + hv.z * q4.z + hv.w * q4.w;
#pragma unroll
        for (int off = 16; off; off >>= 1) p += __shfl_xor_sync(0xffffffffu, p, off);
        if (lane == 0) sc[n] = p;
    }
    __syncthreads();
    if (t < 32) {
        float v = (t < 20) ? sc[t] : -1e30f;
        float m = v;
#pragma unroll
        for (int off = 16; off; off >>= 1) m = fmaxf(m, __shfl_xor_sync(0xffffffffu, m, off));
        float e = (t < 20) ? __expf(v - m) : 0.f;
        float s = e;
#pragma unroll
        for (int off = 16; off; off >>= 1) s += __shfl_xor_sync(0xffffffffu, s, off);
        if (t < 20) ww[t] = e / s;
    }
    __syncthreads();
    float g = 0.f;
#pragma unroll
    for (int n = 0; n < 20; n++) g = fmaf(ww[n], hs[n][t], g);
    gs[t] = g;
    __syncthreads();
    float o = pb[t];
#pragma unroll 8
    for (int k = 0; k < 128; k++) o = fmaf(gs[k], W[k * 128 + t], o);
    out[(size_t)b * 128 + t] = o;
}

// ---------------- launch ----------------------------------------------------
extern "C" void kernel_launch(void* const* d_in, const int* in_sizes, int n_in,
                              void* d_out, int out_size) {
    const float* x     = (const float*)d_in[0];
    const int*   ei    = (const int*)  d_in[1];
    const float* Wl1   = (const float*)d_in[3];
    const float* bl1   = (const float*)d_in[4];
    const float* Wr1   = (const float*)d_in[5];
    const float* br1   = (const float*)d_in[6];
    const float* att1  = (const float*)d_in[7];
    const float* bias1 = (const float*)d_in[8];
    const float* Wl2   = (const float*)d_in[9];
    const float* bl2   = (const float*)d_in[10];
    const float* Wr2   = (const float*)d_in[11];
    const float* br2   = (const float*)d_in[12];
    const float* att2  = (const float*)d_in[13];
    const float* bias2 = (const float*)d_in[14];
    const float* ln1g  = (const float*)d_in[15];
    const float* ln1b  = (const float*)d_in[16];
    const float* ln2g  = (const float*)d_in[17];
    const float* ln2b  = (const float*)d_in[18];
    const float* query = (const float*)d_in[19];
    const float* projW = (const float*)d_in[20];
    const float* projb = (const float*)d_in[21];
    float* out = (float*)d_out;

    // CSR build
    k_init_counts<<<(RN + 255) / 256, 256>>>();
    k_hist<<<(RR * EE + 255) / 256, 256>>>(ei);
    k_scan1<<<SCAN_NB, 256>>>();
    k_scan2<<<1, 256>>>();
    k_scan3<<<SCAN_NB, 256>>>();
    k_scatter<<<(RR * ETOT + 255) / 256, 256>>>(ei);

    dim3 gg(NN / 64, 2 * RR);
    // layer 1
    k_gemm<<<gg, 256>>>(x, 32, Wl1, Wr1, bl1, br1);
    k_gather<<<NN * 32 / 256, 256>>>(att1, bias1, ln1g, ln1b);
    // layer 2
    k_gemm<<<gg, 256>>>(nullptr, 128, Wl2, Wr2, bl2, br2);
    k_gather<<<NN * 32 / 256, 256>>>(att2, bias2, ln2g, ln2b);
    // pooling + projection
    k_pool<<<BGRAPH, 128>>>(query, projW, projb, out);
}